// round 9
// baseline (speedup 1.0000x reference)
#include <cuda_runtime.h>
#include <cstdint>

// ---------------------------------------------------------------------------
// Gazs cell via 3-term two-level int8 IMMA (m16n8k32.s8).
// a = SA*(a_hi + a_lo/128), w = SW*(w_hi + w_lo/128);
// gates = SA*SW*(S_hh + (S_hl + S_lh)/128), lo*lo dropped (negligible).
// Tests the hypothesis that legacy IMMA k32 issues at ~8 cyc/SMSP (2x HMMA).
// ---------------------------------------------------------------------------

#define BM 64
#define BN_GATE 64
#define BN 192                      // 3 gates * 64 cols (B rows)
#define KC 64                       // int8 k per stage (64B rows)
#define NSTAGES 4
#define ROW_BYTES 80                // 64B data + 16B pad
#define OFF_AH 0
#define OFF_AL (BM * ROW_BYTES)             // 5120
#define OFF_BH (2 * BM * ROW_BYTES)         // 10240
#define OFF_BL (OFF_BH + BN * ROW_BYTES)    // 25600
#define STAGE  (OFF_BL + BN * ROW_BYTES)    // 40960
#define DYN_SMEM (NSTAGES * STAGE)          // 163840

#define BATCH 8192
#define HDIM  1024
#define KDIM  4096

// quantization scales (inputs ~N(0,1); W ~N(0,(1/64)^2); 6-sigma range)
#define SA_F (6.0f / 127.0f)
#define SW_F (6.0f / (64.0f * 127.0f))
#define INV_SA (127.0f / 6.0f)
#define INV_SW (127.0f * 64.0f / 6.0f)

__device__ __align__(16) int8_t A8h[(size_t)BATCH * KDIM];
__device__ __align__(16) int8_t A8l[(size_t)BATCH * KDIM];
__device__ __align__(16) int8_t W8h[(size_t)3 * HDIM * KDIM];
__device__ __align__(16) int8_t W8l[(size_t)3 * HDIM * KDIM];

// ---- helpers ---------------------------------------------------------------
__device__ __forceinline__ uint32_t smem_u32(const void* p) {
    uint32_t a;
    asm("{ .reg .u64 t; cvta.to.shared.u64 t, %1; cvt.u32.u64 %0, t; }" : "=r"(a) : "l"(p));
    return a;
}
__device__ __forceinline__ void cp16(uint32_t dst, const void* src) {
    asm volatile("cp.async.cg.shared.global [%0], [%1], 16;" :: "r"(dst), "l"(src));
}
__device__ __forceinline__ void cp_commit() {
    asm volatile("cp.async.commit_group;" ::: "memory");
}
__device__ __forceinline__ void wait_groups(int w) {
    if (w == 0)      asm volatile("cp.async.wait_group 0;" ::: "memory");
    else if (w == 1) asm volatile("cp.async.wait_group 1;" ::: "memory");
    else             asm volatile("cp.async.wait_group 2;" ::: "memory");
}
__device__ __forceinline__ void ldm_x4(uint32_t r[4], uint32_t addr) {
    asm volatile("ldmatrix.sync.aligned.m8n8.x4.shared.b16 {%0,%1,%2,%3}, [%4];"
        : "=r"(r[0]), "=r"(r[1]), "=r"(r[2]), "=r"(r[3]) : "r"(addr));
}
__device__ __forceinline__ void mma_s8(int d[4], const uint32_t a[4],
                                       uint32_t b0, uint32_t b1) {
    asm volatile(
        "mma.sync.aligned.m16n8k32.row.col.s32.s8.s8.s32 "
        "{%0,%1,%2,%3},{%4,%5,%6,%7},{%8,%9},{%0,%1,%2,%3};"
        : "+r"(d[0]), "+r"(d[1]), "+r"(d[2]), "+r"(d[3])
        : "r"(a[0]), "r"(a[1]), "r"(a[2]), "r"(a[3]), "r"(b0), "r"(b1));
}
__device__ __forceinline__ float fast_sigmoid(float v) {
    return __fdividef(1.f, 1.f + __expf(-v));
}
__device__ __forceinline__ float fast_tanh(float v) {
    return 1.f - __fdividef(2.f, __expf(2.f * v) + 1.f);
}

// quantize one float to (hi, lo) int8 pair given inverse scale
__device__ __forceinline__ void q2(float v, float inv, int& hi, int& lo) {
    float t = v * inv;
    float q = rintf(t);
    q = fminf(127.f, fmaxf(-127.f, q));
    float l = rintf((t - q) * 128.f);
    l = fminf(127.f, fmaxf(-127.f, l));
    hi = (int)q;
    lo = (int)l;
}
__device__ __forceinline__ void pack2(const float4& v, float inv,
                                      uint32_t& hi, uint32_t& lo) {
    int h0, l0, h1, l1, h2, l2, h3, l3;
    q2(v.x, inv, h0, l0);
    q2(v.y, inv, h1, l1);
    q2(v.z, inv, h2, l2);
    q2(v.w, inv, h3, l3);
    hi = (uint32_t)(h0 & 255) | ((uint32_t)(h1 & 255) << 8)
       | ((uint32_t)(h2 & 255) << 16) | ((uint32_t)(h3 & 255) << 24);
    lo = (uint32_t)(l0 & 255) | ((uint32_t)(l1 & 255) << 8)
       | ((uint32_t)(l2 & 255) << 16) | ((uint32_t)(l3 & 255) << 24);
}

// ---- phase 1: converter (A rows then W rows, gate-interleaved) ---------------
// W row j, j = b*24 + g*8 + w  (b = n8 block, g = gate, w = col in block)
__global__ void conv_kernel(const float* __restrict__ h, const float* __restrict__ x,
                            const float* __restrict__ glo,
                            const float* __restrict__ Wi, const float* __restrict__ Wf,
                            const float* __restrict__ Wc)
{
    const int bid = blockIdx.x;
    if (bid < BATCH) {
        const int m = bid;
        int8_t* dh = A8h + (size_t)m * KDIM;
        int8_t* dl = A8l + (size_t)m * KDIM;
        const float* h_r = h + (size_t)m * HDIM;
        const float* x_r = x + (size_t)m * 2 * HDIM;
        const float* g_r = glo + (size_t)m * HDIM;
#pragma unroll 1
        for (int f4 = threadIdx.x; f4 < KDIM / 4; f4 += 256) {
            int k = f4 * 4;
            const float* src = (k < HDIM) ? (h_r + k)
                             : (k < 3 * HDIM) ? (x_r + (k - HDIM))
                             : (g_r + (k - 3 * HDIM));
            float4 v = *(const float4*)src;
            uint32_t ph, pl;
            pack2(v, INV_SA, ph, pl);
            *(uint32_t*)(dh + k) = ph;
            *(uint32_t*)(dl + k) = pl;
        }
    } else {
        const int j = bid - BATCH;
        const int b = j / 24, rem = j % 24;
        const int g = rem >> 3, w = rem & 7;
        const int n = b * 8 + w;
        const float* src_r = ((g == 0) ? Wi : (g == 1) ? Wf : Wc) + (size_t)n * KDIM;
        int8_t* dh = W8h + (size_t)j * KDIM;
        int8_t* dl = W8l + (size_t)j * KDIM;
#pragma unroll 1
        for (int f4 = threadIdx.x; f4 < KDIM / 4; f4 += 256) {
            int k = f4 * 4;
            float4 v = *(const float4*)(src_r + k);
            uint32_t ph, pl;
            pack2(v, INV_SW, ph, pl);
            *(uint32_t*)(dh + k) = ph;
            *(uint32_t*)(dl + k) = pl;
        }
    }
}

// ---- phase 2: GEMM + fused epilogue ------------------------------------------
// Per stage: (A hi/lo 64 rows + B hi/lo 192 rows) x 64B, stride 80B; 2048 cp16.
__device__ __forceinline__ void issue_stage(uint32_t sbase, int tid, int kc, int m0, int rbase)
{
    const int k0 = kc * KC;
#pragma unroll
    for (int jj = 0; jj < 8; jj++) {
        int idx = tid + (jj << 8);
        if (idx < 256) {                         // A hi: 64 rows * 4
            int row = idx >> 2, c = idx & 3;
            cp16(sbase + OFF_AH + (uint32_t)row * ROW_BYTES + (uint32_t)c * 16u,
                 A8h + (size_t)(m0 + row) * KDIM + k0 + c * 16);
        } else if (idx < 512) {                  // A lo
            int t = idx - 256;
            int row = t >> 2, c = t & 3;
            cp16(sbase + OFF_AL + (uint32_t)row * ROW_BYTES + (uint32_t)c * 16u,
                 A8l + (size_t)(m0 + row) * KDIM + k0 + c * 16);
        } else if (idx < 1280) {                 // B hi: 192 rows * 4
            int t = idx - 512;
            int row = t >> 2, c = t & 3;
            cp16(sbase + OFF_BH + (uint32_t)row * ROW_BYTES + (uint32_t)c * 16u,
                 W8h + (size_t)(rbase + row) * KDIM + k0 + c * 16);
        } else {                                 // B lo
            int t = idx - 1280;
            int row = t >> 2, c = t & 3;
            cp16(sbase + OFF_BL + (uint32_t)row * ROW_BYTES + (uint32_t)c * 16u,
                 W8l + (size_t)(rbase + row) * KDIM + k0 + c * 16);
        }
    }
    cp_commit();
}

__global__ void __launch_bounds__(256, 1) gazs_gemm_kernel(
    const float* __restrict__ h,
    const float* __restrict__ Wib, const float* __restrict__ Wfb,
    const float* __restrict__ Wcb, float* __restrict__ out)
{
    extern __shared__ __align__(128) char smem[];
    const uint32_t sb = smem_u32(smem);

    const int NC   = KDIM / KC;          // 64
    const int tid  = threadIdx.x;
    const int lane = tid & 31;
    const int wid  = tid >> 5;
    const int wn   = wid & 3;            // 4 n-groups, 48 B-rows each
    const int wm   = wid >> 2;           // 2 m-groups, 32 rows each
    const int m0   = blockIdx.y * BM;
    const int n0   = blockIdx.x * BN_GATE;
    const int rbase = blockIdx.x * BN;   // W8 row base
    const int qr   = lane >> 2;
    const int qc   = lane & 3;

    // ldmatrix per-lane base offsets (same geometry as fp16; 32B = k32 step)
    const uint32_t a_lb = (uint32_t)((wm * 32 + (lane & 15)) * ROW_BYTES + (lane >> 4) * 16);
    const uint32_t b_lb = (uint32_t)((wn * 48 + (lane & 7) + ((lane & 16) ? 8 : 0)) * ROW_BYTES
                                     + ((lane >> 3) & 1) * 16);

    int accHH[2][6][4];     // S_hh
    int accX[2][6][4];      // S_hl + S_lh (shares /128 weight)
#pragma unroll
    for (int mt = 0; mt < 2; mt++)
#pragma unroll
        for (int nt = 0; nt < 6; nt++)
#pragma unroll
            for (int c = 0; c < 4; c++) { accHH[mt][nt][c] = 0; accX[mt][nt][c] = 0; }

    // prologue: 3 stages in flight
#pragma unroll
    for (int s = 0; s < NSTAGES - 1; s++)
        issue_stage(sb + (uint32_t)s * STAGE, tid, s, m0, rbase);

    for (int kc = 0; kc < NC; kc++) {
        int w = NC - 1 - kc; if (w > NSTAGES - 2) w = NSTAGES - 2;
        wait_groups(w);
        __syncthreads();

        int pf = kc + NSTAGES - 1;
        if (pf < NC)
            issue_stage(sb + (uint32_t)(pf & 3) * STAGE, tid, pf, m0, rbase);

        const uint32_t Ss = sb + (uint32_t)(kc & 3) * STAGE;

#pragma unroll
        for (int s = 0; s < 2; s++) {            // two k32 steps per chunk
            uint32_t ah[2][4], al[2][4];
            ldm_x4(ah[0], Ss + OFF_AH + a_lb + (uint32_t)s * 32);
            ldm_x4(ah[1], Ss + OFF_AH + a_lb + (uint32_t)(16 * ROW_BYTES) + (uint32_t)s * 32);
            ldm_x4(al[0], Ss + OFF_AL + a_lb + (uint32_t)s * 32);
            ldm_x4(al[1], Ss + OFF_AL + a_lb + (uint32_t)(16 * ROW_BYTES) + (uint32_t)s * 32);
#pragma unroll
            for (int nb = 0; nb < 3; nb++) {
                uint32_t bh[4], bl[4];
                ldm_x4(bh, Ss + OFF_BH + b_lb + (uint32_t)(nb * 16 * ROW_BYTES) + (uint32_t)s * 32);
                ldm_x4(bl, Ss + OFF_BL + b_lb + (uint32_t)(nb * 16 * ROW_BYTES) + (uint32_t)s * 32);
#pragma unroll
                for (int t = 0; t < 2; t++)
#pragma unroll
                    for (int mt = 0; mt < 2; mt++) {
                        mma_s8(accHH[mt][2 * nb + t], ah[mt], bh[2 * t], bh[2 * t + 1]);
                        mma_s8(accX[mt][2 * nb + t],  ah[mt], bl[2 * t], bl[2 * t + 1]);
                        mma_s8(accX[mt][2 * nb + t],  al[mt], bh[2 * t], bh[2 * t + 1]);
                    }
            }
        }
    }

    // ---- epilogue: dequant + in-register gate blend ------------------------
    const float DQ  = SA_F * SW_F;
    const float DQL = DQ * (1.0f / 128.0f);
#pragma unroll
    for (int mt = 0; mt < 2; mt++) {
        const int rb = m0 + wm * 32 + mt * 16 + qr;
#pragma unroll
        for (int bl = 0; bl < 2; bl++) {
            const int n = n0 + (2 * wn + bl) * 8 + qc * 2;
            const float bi0 = __ldg(Wib + n), bi1 = __ldg(Wib + n + 1);
            const float bf0 = __ldg(Wfb + n), bf1 = __ldg(Wfb + n + 1);
            const float bc0 = __ldg(Wcb + n), bc1 = __ldg(Wcb + n + 1);
            const int* ihh = &accHH[mt][bl * 3 + 0][0];
            const int* ixx = &accX[mt][bl * 3 + 0][0];
            const int* fhh = &accHH[mt][bl * 3 + 1][0];
            const int* fxx = &accX[mt][bl * 3 + 1][0];
            const int* chh = &accHH[mt][bl * 3 + 2][0];
            const int* cxx = &accX[mt][bl * 3 + 2][0];
#pragma unroll
            for (int rs = 0; rs < 2; rs++) {
                const int row = rb + rs * 8;
                const int i0 = rs * 2;
                float2 hv = *(const float2*)(h + (size_t)row * HDIM + n);

                float iv0 = fmaf((float)ixx[i0],     DQL, (float)ihh[i0]     * DQ) + bi0;
                float iv1 = fmaf((float)ixx[i0 + 1], DQL, (float)ihh[i0 + 1] * DQ) + bi1;
                float fv0 = fmaf((float)fxx[i0],     DQL, (float)fhh[i0]     * DQ) + bf0;
                float fv1 = fmaf((float)fxx[i0 + 1], DQL, (float)fhh[i0 + 1] * DQ) + bf1;
                float cv0 = fmaf((float)cxx[i0],     DQL, (float)chh[i0]     * DQ) + bc0;
                float cv1 = fmaf((float)cxx[i0 + 1], DQL, (float)chh[i0 + 1] * DQ) + bc1;

                float ig0 = fast_sigmoid(iv0), ig1 = fast_sigmoid(iv1);
                float fg0 = fast_sigmoid(fv0), fg1 = fast_sigmoid(fv1);
                float cg0 = fast_tanh(cv0),    cg1 = fast_tanh(cv1);
                float al0 = fast_sigmoid(ig0 - fg0);
                float al1 = fast_sigmoid(ig1 - fg1);

                float2 ov;
                ov.x = fmaf(al0, cg0 - hv.x, hv.x);
                ov.y = fmaf(al1, cg1 - hv.y, hv.y);
                *(float2*)(out + (size_t)row * HDIM + n) = ov;
            }
        }
    }
}

extern "C" void kernel_launch(void* const* d_in, const int* in_sizes, int n_in,
                              void* d_out, int out_size)
{
    const float* h   = (const float*)d_in[0];
    const float* x   = (const float*)d_in[1];
    const float* glo = (const float*)d_in[2];
    const float* Wi  = (const float*)d_in[3];
    const float* Wib = (const float*)d_in[4];
    const float* Wf  = (const float*)d_in[5];
    const float* Wfb = (const float*)d_in[6];
    const float* Wc  = (const float*)d_in[7];
    const float* Wcb = (const float*)d_in[8];
    float* out = (float*)d_out;

    cudaFuncSetAttribute(gazs_gemm_kernel,
                         cudaFuncAttributeMaxDynamicSharedMemorySize, DYN_SMEM);

    conv_kernel<<<BATCH + 3 * HDIM, 256>>>(h, x, glo, Wi, Wf, Wc);

    dim3 grid(HDIM / BN_GATE, BATCH / BM);   // (16, 128) = 2048 CTAs
    gazs_gemm_kernel<<<grid, 256, DYN_SMEM>>>(h, Wib, Wfb, Wcb, out);
}

// round 10
// speedup vs baseline: 5.5747x; 5.5747x over previous
#include <cuda_runtime.h>
#include <cuda_fp16.h>
#include <cstdint>

// ---------------------------------------------------------------------------
// Gazs cell, legacy tensor-core path, fp16 in / fp32 accum.
// R10: R5 mainloop (at the mma.sync issue floor ~16 cyc/SMSP) with A
// converted fp32->fp16 ON THE FLY in smem (stage kc+1 converted while
// MMAing stage kc; zero extra barriers). Conv kernel is W-only.
// ---------------------------------------------------------------------------

#define BM 128
#define BN_GATE 128
#define BN 384                     // 3 gates * 128 cols (B rows)
#define KC 32                      // k elements per stage
#define NSTAGES 4
#define ROW_BYTES 80               // fp16 tile row: 64B data + 16B pad
#define A32_BYTES (BM * 128)               // 16384 (32 fp32 = 128B rows, no pad)
#define A16_BYTES (BM * ROW_BYTES)         // 10240
#define B_BYTES   (BN * ROW_BYTES)         // 30720
#define OFF_A32 0
#define OFF_A16 A32_BYTES                  // 16384
#define OFF_B   (A32_BYTES + A16_BYTES)    // 26624
#define STAGE   (OFF_B + B_BYTES)          // 57344
#define DYN_SMEM (NSTAGES * STAGE)         // 229376 (< 232448 opt-in max)

#define BATCH 8192
#define HDIM  1024
#define KDIM  4096

__device__ __align__(16) __half W16[(size_t)3 * HDIM * KDIM];

// ---- helpers ---------------------------------------------------------------
__device__ __forceinline__ uint32_t smem_u32(const void* p) {
    uint32_t a;
    asm("{ .reg .u64 t; cvta.to.shared.u64 t, %1; cvt.u32.u64 %0, t; }" : "=r"(a) : "l"(p));
    return a;
}
__device__ __forceinline__ void cp16(uint32_t dst, const void* src) {
    asm volatile("cp.async.cg.shared.global [%0], [%1], 16;" :: "r"(dst), "l"(src));
}
__device__ __forceinline__ void cp_commit() {
    asm volatile("cp.async.commit_group;" ::: "memory");
}
__device__ __forceinline__ void wait_groups(int w) {
    if (w == 0)      asm volatile("cp.async.wait_group 0;" ::: "memory");
    else if (w == 1) asm volatile("cp.async.wait_group 1;" ::: "memory");
    else             asm volatile("cp.async.wait_group 2;" ::: "memory");
}
__device__ __forceinline__ void ldm_x4(uint32_t r[4], uint32_t addr) {
    asm volatile("ldmatrix.sync.aligned.m8n8.x4.shared.b16 {%0,%1,%2,%3}, [%4];"
        : "=r"(r[0]), "=r"(r[1]), "=r"(r[2]), "=r"(r[3]) : "r"(addr));
}
__device__ __forceinline__ void mma_f16(float d[4], const uint32_t a[4],
                                        uint32_t b0, uint32_t b1) {
    asm volatile(
        "mma.sync.aligned.m16n8k16.row.col.f32.f16.f16.f32 "
        "{%0,%1,%2,%3},{%4,%5,%6,%7},{%8,%9},{%0,%1,%2,%3};"
        : "+f"(d[0]), "+f"(d[1]), "+f"(d[2]), "+f"(d[3])
        : "r"(a[0]), "r"(a[1]), "r"(a[2]), "r"(a[3]), "r"(b0), "r"(b1));
}
__device__ __forceinline__ float fast_sigmoid(float v) {
    return __fdividef(1.f, 1.f + __expf(-v));
}
__device__ __forceinline__ float fast_tanh(float v) {
    return 1.f - __fdividef(2.f, __expf(2.f * v) + 1.f);
}

// ---- phase 1: W converter only (gate-interleaved) ---------------------------
// W16 row j, j = b*24 + g*8 + w  (b = n8 block, g = gate, w = col in block)
__global__ void conv_w_kernel(const float* __restrict__ Wi, const float* __restrict__ Wf,
                              const float* __restrict__ Wc)
{
    const int j = blockIdx.x;
    const int b = j / 24, rem = j % 24;
    const int g = rem >> 3, w = rem & 7;
    const int n = b * 8 + w;
    const float* src_r = ((g == 0) ? Wi : (g == 1) ? Wf : Wc) + (size_t)n * KDIM;
    __half* dst = W16 + (size_t)j * KDIM;
#pragma unroll 1
    for (int f4 = threadIdx.x; f4 < KDIM / 4; f4 += 256) {
        int k = f4 * 4;
        float4 v = *(const float4*)(src_r + k);
        __half2 p0 = __floats2half2_rn(v.x, v.y);
        __half2 p1 = __floats2half2_rn(v.z, v.w);
        uint2 u;
        u.x = *(const uint32_t*)&p0;
        u.y = *(const uint32_t*)&p1;
        *(uint2*)(dst + k) = u;
    }
}

// ---- phase 2: GEMM + fused epilogue ------------------------------------------
// Per stage: A32 128 rows x 128B (raw fp32) + B 384 rows x 64B fp16; 2560 cp16.
__device__ __forceinline__ void issue_stage(
    uint32_t sbase, int tid, int kc, int m0, int rbase, int,
    const float* __restrict__ h, const float* __restrict__ x,
    const float* __restrict__ glo)
{
    const int k0 = kc * KC;
    const float* ab; int astr, ac;
    if (k0 < HDIM)          { ab = h;   astr = HDIM;     ac = k0; }
    else if (k0 < 3 * HDIM) { ab = x;   astr = 2 * HDIM; ac = k0 - HDIM; }
    else                    { ab = glo; astr = HDIM;     ac = k0 - 3 * HDIM; }
#pragma unroll
    for (int jj = 0; jj < 5; jj++) {
        int idx = tid + (jj << 9);
        if (idx < 1024) {                       // A32: 128 rows * 8 x 16B
            int row = idx >> 3, c = idx & 7;
            cp16(sbase + OFF_A32 + (uint32_t)row * 128u + (uint32_t)c * 16u,
                 ab + (size_t)(m0 + row) * astr + ac + c * 4);
        } else {                                // B: 384 rows * 4 x 16B
            int t = idx - 1024;
            int row = t >> 2, c = t & 3;
            cp16(sbase + OFF_B + (uint32_t)row * ROW_BYTES + (uint32_t)c * 16u,
                 W16 + (size_t)(rbase + row) * KDIM + kc * KC + c * 8);
        }
    }
    cp_commit();
}

// Convert one stage's A32 -> A16 in smem (all 512 threads; 2 float4 each).
__device__ __forceinline__ void convert_a(uint32_t sbase, int tid)
{
#pragma unroll
    for (int j = 0; j < 2; j++) {
        int idx = tid + (j << 9);               // 0..1023
        int row = idx >> 3, g = idx & 7;
        float4 v = *(const float4*)(uintptr_t)0;    // placeholder (rewritten below)
        (void)v;
        // LDS float4
        float4 a;
        asm volatile("ld.shared.v4.f32 {%0,%1,%2,%3}, [%4];"
            : "=f"(a.x), "=f"(a.y), "=f"(a.z), "=f"(a.w)
            : "r"(sbase + OFF_A32 + (uint32_t)row * 128u + (uint32_t)g * 16u));
        __half2 p0 = __floats2half2_rn(a.x, a.y);
        __half2 p1 = __floats2half2_rn(a.z, a.w);
        uint32_t u0 = *(const uint32_t*)&p0;
        uint32_t u1 = *(const uint32_t*)&p1;
        asm volatile("st.shared.v2.b32 [%0], {%1,%2};"
            :: "r"(sbase + OFF_A16 + (uint32_t)row * ROW_BYTES + (uint32_t)g * 8u),
               "r"(u0), "r"(u1) : "memory");
    }
}

__global__ void __launch_bounds__(512, 1) gazs_gemm_kernel(
    const float* __restrict__ h, const float* __restrict__ x,
    const float* __restrict__ glo,
    const float* __restrict__ Wib, const float* __restrict__ Wfb,
    const float* __restrict__ Wcb, float* __restrict__ out)
{
    extern __shared__ __align__(128) char smem[];
    const uint32_t sb = smem_u32(smem);

    const int NC   = KDIM / KC;          // 128
    const int tid  = threadIdx.x;
    const int lane = tid & 31;
    const int wid  = tid >> 5;
    const int wn   = wid & 3;            // 4 n-groups, 96 B-rows each
    const int wm   = wid >> 2;           // 4 m-groups, 32 rows each
    const int m0   = blockIdx.y * BM;
    const int n0   = blockIdx.x * BN_GATE;
    const int rbase = blockIdx.x * BN;   // W16 row base
    const int qr   = lane >> 2;
    const int qc   = lane & 3;

    const uint32_t a_lb = (uint32_t)((wm * 32 + (lane & 15)) * ROW_BYTES + (lane >> 4) * 16);
    const uint32_t b_lb = (uint32_t)((wn * 96 + (lane & 7) + ((lane & 16) ? 8 : 0)) * ROW_BYTES
                                     + ((lane >> 3) & 1) * 16);

    float acc[2][12][4];
#pragma unroll
    for (int mt = 0; mt < 2; mt++)
#pragma unroll
        for (int nt = 0; nt < 12; nt++)
#pragma unroll
            for (int c = 0; c < 4; c++) acc[mt][nt][c] = 0.f;

    // ---- prologue: 3 stages in flight; convert stage 0 --------------------
#pragma unroll
    for (int s = 0; s < NSTAGES - 1; s++)
        issue_stage(sb + (uint32_t)s * STAGE, tid, s, m0, rbase, 0, h, x, glo);
    wait_groups(2);                 // stage 0 arrived
    __syncthreads();
    convert_a(sb + 0 * STAGE, tid);

    for (int kc = 0; kc < NC; kc++) {
        // need stages <= kc+1 arrived (kc for MMA, kc+1 for conversion)
        int w = (kc < NC - 2) ? 1 : 0;
        wait_groups(w);
        __syncthreads();            // also publishes A16(kc) converted last iter

        int pf = kc + NSTAGES - 1;
        if (pf < NC)                // overwrites slot (kc-1)%4: consumed pre-sync
            issue_stage(sb + (uint32_t)(pf & 3) * STAGE, tid, pf, m0, rbase, 0, h, x, glo);

        if (kc + 1 < NC)            // convert next stage's A while MMAing this one
            convert_a(sb + (uint32_t)((kc + 1) & 3) * STAGE, tid);

        const uint32_t As = sb + (uint32_t)(kc & 3) * STAGE + OFF_A16;
        const uint32_t Bs = sb + (uint32_t)(kc & 3) * STAGE + OFF_B;

#pragma unroll
        for (int s = 0; s < 2; s++) {
            uint32_t a0[4], a1[4];
            ldm_x4(a0, As + a_lb + (uint32_t)s * 32);
            ldm_x4(a1, As + a_lb + (uint32_t)(16 * ROW_BYTES) + (uint32_t)s * 32);

            uint32_t bcur[4], bnxt[4];
            ldm_x4(bcur, Bs + b_lb + (uint32_t)s * 32);
#pragma unroll
            for (int nb = 0; nb < 6; nb++) {
                if (nb < 5)
                    ldm_x4(bnxt, Bs + b_lb + (uint32_t)((nb + 1) * 16 * ROW_BYTES)
                                 + (uint32_t)s * 32);
                mma_f16(acc[0][2 * nb],     a0, bcur[0], bcur[1]);
                mma_f16(acc[0][2 * nb + 1], a0, bcur[2], bcur[3]);
                mma_f16(acc[1][2 * nb],     a1, bcur[0], bcur[1]);
                mma_f16(acc[1][2 * nb + 1], a1, bcur[2], bcur[3]);
#pragma unroll
                for (int q = 0; q < 4; q++) bcur[q] = bnxt[q];
            }
        }
    }

    // ---- epilogue: in-register gate blend ----------------------------------
#pragma unroll
    for (int mt = 0; mt < 2; mt++) {
        const int rb = m0 + wm * 32 + mt * 16 + qr;
#pragma unroll
        for (int bl = 0; bl < 4; bl++) {
            const int n = n0 + (wn * 4 + bl) * 8 + qc * 2;
            const float bi0 = __ldg(Wib + n), bi1 = __ldg(Wib + n + 1);
            const float bf0 = __ldg(Wfb + n), bf1 = __ldg(Wfb + n + 1);
            const float bc0 = __ldg(Wcb + n), bc1 = __ldg(Wcb + n + 1);
            const float* ai = acc[mt][bl * 3 + 0];
            const float* af = acc[mt][bl * 3 + 1];
            const float* ac = acc[mt][bl * 3 + 2];
#pragma unroll
            for (int rs = 0; rs < 2; rs++) {
                const int row = rb + rs * 8;
                const int i0 = rs * 2;
                float2 hv = *(const float2*)(h + (size_t)row * HDIM + n);

                float ig0 = fast_sigmoid(ai[i0] + bi0);
                float ig1 = fast_sigmoid(ai[i0 + 1] + bi1);
                float fg0 = fast_sigmoid(af[i0] + bf0);
                float fg1 = fast_sigmoid(af[i0 + 1] + bf1);
                float cg0 = fast_tanh(ac[i0] + bc0);
                float cg1 = fast_tanh(ac[i0 + 1] + bc1);
                float al0 = fast_sigmoid(ig0 - fg0);
                float al1 = fast_sigmoid(ig1 - fg1);

                float2 ov;
                ov.x = fmaf(al0, cg0 - hv.x, hv.x);
                ov.y = fmaf(al1, cg1 - hv.y, hv.y);
                *(float2*)(out + (size_t)row * HDIM + n) = ov;
            }
        }
    }
}

extern "C" void kernel_launch(void* const* d_in, const int* in_sizes, int n_in,
                              void* d_out, int out_size)
{
    const float* h   = (const float*)d_in[0];
    const float* x   = (const float*)d_in[1];
    const float* glo = (const float*)d_in[2];
    const float* Wi  = (const float*)d_in[3];
    const float* Wib = (const float*)d_in[4];
    const float* Wf  = (const float*)d_in[5];
    const float* Wfb = (const float*)d_in[6];
    const float* Wc  = (const float*)d_in[7];
    const float* Wcb = (const float*)d_in[8];
    float* out = (float*)d_out;

    cudaFuncSetAttribute(gazs_gemm_kernel,
                         cudaFuncAttributeMaxDynamicSharedMemorySize, DYN_SMEM);

    conv_w_kernel<<<3 * HDIM, 256>>>(Wi, Wf, Wc);

    dim3 grid(HDIM / BN_GATE, BATCH / BM);   // (8, 64) = 512 CTAs
    gazs_gemm_kernel<<<grid, 512, DYN_SMEM>>>(h, x, glo, Wib, Wfb, Wcb, out);
}

// round 11
// speedup vs baseline: 6.2263x; 1.1169x over previous
#include <cuda_runtime.h>
#include <cuda_fp16.h>
#include <cstdint>

// ---------------------------------------------------------------------------
// Gazs cell, legacy tensor-core path, fp16 in / fp32 accum.
// R11: GEMM = R5 verbatim (measured at the mma.sync issue floor,
// ~16.2 cyc/SMSP; every mainloop modification regressed it).
// Conv: grid-stride (1184 CTAs), __ldcs streaming reads to keep the fp16
// outputs resident in L2 for the GEMM's cp.async stream.
// ---------------------------------------------------------------------------

#define BM 128
#define BN_GATE 128
#define BN 384                     // 3 gates * 128 cols (B rows)
#define KC 32                      // fp16 k per stage (64B rows)
#define NSTAGES 4
#define ROW_BYTES 80               // 64B data + 16B pad
#define A_TILE (BM * ROW_BYTES)            // 10240
#define B_TILE (BN * ROW_BYTES)            // 30720
#define STAGE  (A_TILE + B_TILE)           // 40960
#define DYN_SMEM (NSTAGES * STAGE)         // 163840

#define BATCH 8192
#define HDIM  1024
#define KDIM  4096
#define TOT_ROWS (BATCH + 3 * HDIM)        // 11264

__device__ __align__(16) __half A16[(size_t)BATCH * KDIM];
__device__ __align__(16) __half W16[(size_t)3 * HDIM * KDIM];

// ---- helpers ---------------------------------------------------------------
__device__ __forceinline__ uint32_t smem_u32(const void* p) {
    uint32_t a;
    asm("{ .reg .u64 t; cvta.to.shared.u64 t, %1; cvt.u32.u64 %0, t; }" : "=r"(a) : "l"(p));
    return a;
}
__device__ __forceinline__ void cp16(uint32_t dst, const void* src) {
    asm volatile("cp.async.cg.shared.global [%0], [%1], 16;" :: "r"(dst), "l"(src));
}
__device__ __forceinline__ void cp_commit() {
    asm volatile("cp.async.commit_group;" ::: "memory");
}
__device__ __forceinline__ void wait_groups(int w) {
    if (w == 0)      asm volatile("cp.async.wait_group 0;" ::: "memory");
    else if (w == 1) asm volatile("cp.async.wait_group 1;" ::: "memory");
    else             asm volatile("cp.async.wait_group 2;" ::: "memory");
}
__device__ __forceinline__ void ldm_x4(uint32_t r[4], uint32_t addr) {
    asm volatile("ldmatrix.sync.aligned.m8n8.x4.shared.b16 {%0,%1,%2,%3}, [%4];"
        : "=r"(r[0]), "=r"(r[1]), "=r"(r[2]), "=r"(r[3]) : "r"(addr));
}
__device__ __forceinline__ void mma_f16(float d[4], const uint32_t a[4],
                                        uint32_t b0, uint32_t b1) {
    asm volatile(
        "mma.sync.aligned.m16n8k16.row.col.f32.f16.f16.f32 "
        "{%0,%1,%2,%3},{%4,%5,%6,%7},{%8,%9},{%0,%1,%2,%3};"
        : "+f"(d[0]), "+f"(d[1]), "+f"(d[2]), "+f"(d[3])
        : "r"(a[0]), "r"(a[1]), "r"(a[2]), "r"(a[3]), "r"(b0), "r"(b1));
}
__device__ __forceinline__ float fast_sigmoid(float v) {
    return __fdividef(1.f, 1.f + __expf(-v));
}
__device__ __forceinline__ float fast_tanh(float v) {
    return 1.f - __fdividef(2.f, __expf(2.f * v) + 1.f);
}
__device__ __forceinline__ float4 ldcs4(const float* p) {
    float4 v;
    asm volatile("ld.global.cs.v4.f32 {%0,%1,%2,%3}, [%4];"
        : "=f"(v.x), "=f"(v.y), "=f"(v.z), "=f"(v.w) : "l"(p));
    return v;
}

// ---- phase 1: converter, grid-stride over 11264 rows -------------------------
// rows [0, 8192): A = [h|x|glo]; rows [8192, 11264): W, gate-interleaved:
// W16 row j, j = b*24 + g*8 + w  (b = n8 block, g = gate, w = col in block)
__global__ void conv_kernel(const float* __restrict__ h, const float* __restrict__ x,
                            const float* __restrict__ glo,
                            const float* __restrict__ Wi, const float* __restrict__ Wf,
                            const float* __restrict__ Wc)
{
#pragma unroll 1
    for (int row = blockIdx.x; row < TOT_ROWS; row += gridDim.x) {
        if (row < BATCH) {
            const int m = row;
            __half* dst = A16 + (size_t)m * KDIM;
            const float* h_r = h + (size_t)m * HDIM;
            const float* x_r = x + (size_t)m * 2 * HDIM;
            const float* g_r = glo + (size_t)m * HDIM;
#pragma unroll 1
            for (int f4 = threadIdx.x; f4 < KDIM / 4; f4 += 256) {
                int k = f4 * 4;
                const float* src = (k < HDIM) ? (h_r + k)
                                 : (k < 3 * HDIM) ? (x_r + (k - HDIM))
                                 : (g_r + (k - 3 * HDIM));
                float4 v = ldcs4(src);
                __half2 p0 = __floats2half2_rn(v.x, v.y);
                __half2 p1 = __floats2half2_rn(v.z, v.w);
                uint2 u;
                u.x = *(const uint32_t*)&p0;
                u.y = *(const uint32_t*)&p1;
                *(uint2*)(dst + k) = u;
            }
        } else {
            const int j = row - BATCH;
            const int b = j / 24, rem = j % 24;
            const int g = rem >> 3, w = rem & 7;
            const int n = b * 8 + w;
            const float* src_r = ((g == 0) ? Wi : (g == 1) ? Wf : Wc) + (size_t)n * KDIM;
            __half* dst = W16 + (size_t)j * KDIM;
#pragma unroll 1
            for (int f4 = threadIdx.x; f4 < KDIM / 4; f4 += 256) {
                int k = f4 * 4;
                float4 v = ldcs4(src_r + k);
                __half2 p0 = __floats2half2_rn(v.x, v.y);
                __half2 p1 = __floats2half2_rn(v.z, v.w);
                uint2 u;
                u.x = *(const uint32_t*)&p0;
                u.y = *(const uint32_t*)&p1;
                *(uint2*)(dst + k) = u;
            }
        }
    }
}

// ---- phase 2: GEMM + fused epilogue (R5 verbatim) -----------------------------
// Per stage: A 128 rows x 64B + B 384 rows x 64B, stride 80B; 2048 cp16.
__device__ __forceinline__ void issue_stage(uint32_t sbase, int tid, int kc, int m0, int rbase)
{
    const int k0 = kc * KC;
#pragma unroll
    for (int jj = 0; jj < 4; jj++) {
        int idx = tid + (jj << 9);
        if (idx < 512) {                        // A tile: 128 rows * 4
            int row = idx >> 2, c = idx & 3;
            const __half* src = A16 + (size_t)(m0 + row) * KDIM + k0 + c * 8;
            cp16(sbase + (uint32_t)row * ROW_BYTES + (uint32_t)c * 16u, src);
        } else {                                // B tile: 384 rows * 4
            int t = idx - 512;
            int row = t >> 2, c = t & 3;
            const __half* src = W16 + (size_t)(rbase + row) * KDIM + k0 + c * 8;
            cp16(sbase + A_TILE + (uint32_t)row * ROW_BYTES + (uint32_t)c * 16u, src);
        }
    }
    cp_commit();
}

__global__ void __launch_bounds__(512, 1) gazs_gemm_kernel(
    const float* __restrict__ h,
    const float* __restrict__ Wib, const float* __restrict__ Wfb,
    const float* __restrict__ Wcb, float* __restrict__ out)
{
    extern __shared__ __align__(128) char smem[];
    const uint32_t sb = smem_u32(smem);

    const int NC   = KDIM / KC;          // 128
    const int tid  = threadIdx.x;
    const int lane = tid & 31;
    const int wid  = tid >> 5;
    const int wn   = wid & 3;            // 4 n-groups, 96 B-rows each
    const int wm   = wid >> 2;           // 4 m-groups, 32 rows each
    const int m0   = blockIdx.y * BM;
    const int n0   = blockIdx.x * BN_GATE;
    const int rbase = blockIdx.x * BN;   // W16 row base
    const int qr   = lane >> 2;
    const int qc   = lane & 3;

    const uint32_t a_lb = (uint32_t)((wm * 32 + (lane & 15)) * ROW_BYTES + (lane >> 4) * 16);
    const uint32_t b_lb = (uint32_t)((wn * 96 + (lane & 7) + ((lane & 16) ? 8 : 0)) * ROW_BYTES
                                     + ((lane >> 3) & 1) * 16);

    float acc[2][12][4];
#pragma unroll
    for (int mt = 0; mt < 2; mt++)
#pragma unroll
        for (int nt = 0; nt < 12; nt++)
#pragma unroll
            for (int c = 0; c < 4; c++) acc[mt][nt][c] = 0.f;

    // prologue: 3 stages in flight
#pragma unroll
    for (int s = 0; s < NSTAGES - 1; s++)
        issue_stage(sb + (uint32_t)s * STAGE, tid, s, m0, rbase);

    for (int kc = 0; kc < NC; kc++) {
        int w = NC - 1 - kc; if (w > NSTAGES - 2) w = NSTAGES - 2;
        wait_groups(w);
        __syncthreads();

        int pf = kc + NSTAGES - 1;
        if (pf < NC)
            issue_stage(sb + (uint32_t)(pf & 3) * STAGE, tid, pf, m0, rbase);

        const uint32_t As = sb + (uint32_t)(kc & 3) * STAGE;
        const uint32_t Bs = As + A_TILE;

#pragma unroll
        for (int s = 0; s < 2; s++) {
            uint32_t a0[4], a1[4];
            ldm_x4(a0, As + a_lb + (uint32_t)s * 32);
            ldm_x4(a1, As + a_lb + (uint32_t)(16 * ROW_BYTES) + (uint32_t)s * 32);

            uint32_t bcur[4], bnxt[4];
            ldm_x4(bcur, Bs + b_lb + (uint32_t)s * 32);
#pragma unroll
            for (int nb = 0; nb < 6; nb++) {
                if (nb < 5)
                    ldm_x4(bnxt, Bs + b_lb + (uint32_t)((nb + 1) * 16 * ROW_BYTES)
                                 + (uint32_t)s * 32);
                mma_f16(acc[0][2 * nb],     a0, bcur[0], bcur[1]);
                mma_f16(acc[0][2 * nb + 1], a0, bcur[2], bcur[3]);
                mma_f16(acc[1][2 * nb],     a1, bcur[0], bcur[1]);
                mma_f16(acc[1][2 * nb + 1], a1, bcur[2], bcur[3]);
#pragma unroll
                for (int q = 0; q < 4; q++) bcur[q] = bnxt[q];
            }
        }
    }

    // ---- epilogue: in-register gate blend --------------------------------
#pragma unroll
    for (int mt = 0; mt < 2; mt++) {
        const int rb = m0 + wm * 32 + mt * 16 + qr;
#pragma unroll
        for (int bl = 0; bl < 4; bl++) {
            const int n = n0 + (wn * 4 + bl) * 8 + qc * 2;
            const float bi0 = __ldg(Wib + n), bi1 = __ldg(Wib + n + 1);
            const float bf0 = __ldg(Wfb + n), bf1 = __ldg(Wfb + n + 1);
            const float bc0 = __ldg(Wcb + n), bc1 = __ldg(Wcb + n + 1);
            const float* ai = acc[mt][bl * 3 + 0];
            const float* af = acc[mt][bl * 3 + 1];
            const float* ac = acc[mt][bl * 3 + 2];
#pragma unroll
            for (int rs = 0; rs < 2; rs++) {
                const int row = rb + rs * 8;
                const int i0 = rs * 2;
                float2 hv = *(const float2*)(h + (size_t)row * HDIM + n);

                float ig0 = fast_sigmoid(ai[i0] + bi0);
                float ig1 = fast_sigmoid(ai[i0 + 1] + bi1);
                float fg0 = fast_sigmoid(af[i0] + bf0);
                float fg1 = fast_sigmoid(af[i0 + 1] + bf1);
                float cg0 = fast_tanh(ac[i0] + bc0);
                float cg1 = fast_tanh(ac[i0 + 1] + bc1);
                float al0 = fast_sigmoid(ig0 - fg0);
                float al1 = fast_sigmoid(ig1 - fg1);

                float2 ov;
                ov.x = fmaf(al0, cg0 - hv.x, hv.x);
                ov.y = fmaf(al1, cg1 - hv.y, hv.y);
                *(float2*)(out + (size_t)row * HDIM + n) = ov;
            }
        }
    }
}

extern "C" void kernel_launch(void* const* d_in, const int* in_sizes, int n_in,
                              void* d_out, int out_size)
{
    const float* h   = (const float*)d_in[0];
    const float* x   = (const float*)d_in[1];
    const float* glo = (const float*)d_in[2];
    const float* Wi  = (const float*)d_in[3];
    const float* Wib = (const float*)d_in[4];
    const float* Wf  = (const float*)d_in[5];
    const float* Wfb = (const float*)d_in[6];
    const float* Wc  = (const float*)d_in[7];
    const float* Wcb = (const float*)d_in[8];
    float* out = (float*)d_out;

    cudaFuncSetAttribute(gazs_gemm_kernel,
                         cudaFuncAttributeMaxDynamicSharedMemorySize, DYN_SMEM);

    conv_kernel<<<1184, 256>>>(h, x, glo, Wi, Wf, Wc);   // 8 CTAs/SM, grid-stride

    dim3 grid(HDIM / BN_GATE, BATCH / BM);   // (8, 64) = 512 CTAs
    gazs_gemm_kernel<<<grid, 512, DYN_SMEM>>>(h, Wib, Wfb, Wcb, out);
}